// round 1
// baseline (speedup 1.0000x reference)
#include <cuda_runtime.h>

// Problem constants (fixed by setup_inputs)
#define FEA      64
#define NB       16
#define NPATCH   42
#define NVARS    21
#define NTOT     (NB * NPATCH * NVARS)      /* 14112 */
#define COST_IDX (NTOT * FEA)               /* 903168 */
#define INV_CNT  (1.0f / (14112.0f * 4096.0f))

// One-time global scratch: W transposed, Wt[g][h] = W[h][g]
__device__ float g_Wt[FEA * FEA];

// Prep: transpose W into g_Wt (coalesced writes) and zero the cost slot(s).
// Runs at the head of the graph every replay -> idempotent accumulation.
__global__ void ot_prep_kernel(const float* __restrict__ W,
                               float* __restrict__ out, int out_size) {
    int t = blockIdx.x * blockDim.x + threadIdx.x;
    if (t < FEA * FEA) {
        int g = t >> 6;
        int h = t & 63;
        g_Wt[t] = W[h * FEA + g];
    }
    if (t == 0) {
        for (int i = COST_IDX; i < out_size; ++i) out[i] = 0.0f;
    }
}

// Main fused kernel: one CTA (128 threads) per n.
// Thread (tr, tc): tr = tid/16 in [0,8), tc = tid%16 in [0,16).
// Owns rows r0..r0+7 (r0 = 8*tr) and cols c0..c0+3 (c0 = 4*tc) of the 64x64 tile.
// Lanes 0-15 / 16-31 of a warp share a tr group -> LN/softmax reductions are
// 16-lane shuffle reductions, Pl never returns to smem.
__global__ __launch_bounds__(128) void ot_main_kernel(
    const float* __restrict__ x, const float* __restrict__ P,
    const float* __restrict__ mask, const float* __restrict__ bias,
    const float* __restrict__ gamma, const float* __restrict__ beta,
    float* __restrict__ out, int out_size) {

    __shared__ float As[FEA][68];     // P[n] row-major (f, g), padded
    __shared__ float Ws[FEA][68];     // Wt (g, h), padded
    __shared__ float txbuf[8][FEA];   // tx partial per tr-group
    __shared__ float xs[FEA];         // x row for this n
    __shared__ float cbuf[4];         // per-warp cost partials

    const int n    = blockIdx.x;
    const int tid  = threadIdx.x;
    const int lane = tid & 31;
    const int warp = tid >> 5;
    const int tr   = tid >> 4;        // 0..7
    const int tc   = tid & 15;        // 0..15
    const int r0   = tr << 3;
    const int c0   = tc << 2;

    // n -> (b, v, p); x offset == out offset for this n's row
    const int b  = n / (NVARS * NPATCH);
    const int rm = n - b * (NVARS * NPATCH);
    const int v  = rm / NPATCH;
    const int p  = rm - v * NPATCH;
    const long long xoff = (((long long)b * NPATCH + p) * NVARS + v) * FEA;

    // ---- Load tiles (coalesced LDG.128, conflict-free STS.128) ----
    const float4* P4 = reinterpret_cast<const float4*>(P) + (long long)n * (FEA * FEA / 4);
    const float4* W4 = reinterpret_cast<const float4*>(g_Wt);
#pragma unroll
    for (int k = 0; k < 8; ++k) {
        int idx = tid + k * 128;           // float4 index 0..1023
        int r  = idx >> 4;
        int c4 = (idx & 15) << 2;
        float4 pv = P4[idx];
        *reinterpret_cast<float4*>(&As[r][c4]) = pv;
        float4 wv = W4[idx];
        *reinterpret_cast<float4*>(&Ws[r][c4]) = wv;
    }
    if (tid < FEA) xs[tid] = x[xoff + tid];
    __syncthreads();

    // ---- GEMM: acc[i][j] = sum_g P[r0+i][g] * W[c0+j][g] ----
    float acc[8][4];
#pragma unroll
    for (int i = 0; i < 8; ++i) {
        acc[i][0] = 0.f; acc[i][1] = 0.f; acc[i][2] = 0.f; acc[i][3] = 0.f;
    }
#pragma unroll 4
    for (int g = 0; g < FEA; ++g) {
        float4 wv = *reinterpret_cast<const float4*>(&Ws[g][c0]);
#pragma unroll
        for (int i = 0; i < 8; ++i) {
            float a = As[r0 + i][g];       // half-warp broadcast
            acc[i][0] = fmaf(a, wv.x, acc[i][0]);
            acc[i][1] = fmaf(a, wv.y, acc[i][1]);
            acc[i][2] = fmaf(a, wv.z, acc[i][2]);
            acc[i][3] = fmaf(a, wv.w, acc[i][3]);
        }
    }

    // ---- Epilogue: bias + LayerNorm + softmax + tx/cost partials ----
    const float4 bv = *reinterpret_cast<const float4*>(bias  + c0);
    const float4 gv = *reinterpret_cast<const float4*>(gamma + c0);
    const float4 be = *reinterpret_cast<const float4*>(beta  + c0);
    const float4 mv = *reinterpret_cast<const float4*>(mask + (long long)n * FEA + c0);

    float txp0 = 0.f, txp1 = 0.f, txp2 = 0.f, txp3 = 0.f;
    float costp = 0.f;

#pragma unroll
    for (int i = 0; i < 8; ++i) {
        float t0 = acc[i][0] + bv.x;
        float t1 = acc[i][1] + bv.y;
        float t2 = acc[i][2] + bv.z;
        float t3 = acc[i][3] + bv.w;

        // mean / var over the 64-wide row (16 lanes x 4 vals)
        float s1 = t0 + t1 + t2 + t3;
        float s2 = t0*t0 + t1*t1 + t2*t2 + t3*t3;
#pragma unroll
        for (int m = 1; m < 16; m <<= 1) {
            s1 += __shfl_xor_sync(0xffffffffu, s1, m);
            s2 += __shfl_xor_sync(0xffffffffu, s2, m);
        }
        float mu   = s1 * (1.0f / 64.0f);
        float var  = s2 * (1.0f / 64.0f) - mu * mu;
        float rstd = rsqrtf(var + 1e-5f);

        t0 = (t0 - mu) * rstd * gv.x + be.x;
        t1 = (t1 - mu) * rstd * gv.y + be.y;
        t2 = (t2 - mu) * rstd * gv.z + be.z;
        t3 = (t3 - mu) * rstd * gv.w + be.w;

        // softmax over the row
        float mx = fmaxf(fmaxf(t0, t1), fmaxf(t2, t3));
#pragma unroll
        for (int m = 1; m < 16; m <<= 1)
            mx = fmaxf(mx, __shfl_xor_sync(0xffffffffu, mx, m));

        float e0 = __expf(t0 - mx);
        float e1 = __expf(t1 - mx);
        float e2 = __expf(t2 - mx);
        float e3 = __expf(t3 - mx);
        float se = e0 + e1 + e2 + e3;
#pragma unroll
        for (int m = 1; m < 16; m <<= 1)
            se += __shfl_xor_sync(0xffffffffu, se, m);
        float inv = __fdividef(1.0f, se);
        e0 *= inv; e1 *= inv; e2 *= inv; e3 *= inv;

        // tx[g] += xf[f] * Ps[f][g]
        float xf = xs[r0 + i];
        txp0 = fmaf(xf, e0, txp0);
        txp1 = fmaf(xf, e1, txp1);
        txp2 = fmaf(xf, e2, txp2);
        txp3 = fmaf(xf, e3, txp3);

        // cost partial: Ps[f][h] * mask[n][h]
        costp += e0 * mv.x + e1 * mv.y + e2 * mv.z + e3 * mv.w;
    }

    // ---- Reduce tx across the 8 tr-groups via smem ----
    *reinterpret_cast<float4*>(&txbuf[tr][c0]) = make_float4(txp0, txp1, txp2, txp3);
    __syncthreads();
    if (tid < FEA) {
        float s = 0.f;
#pragma unroll
        for (int k = 0; k < 8; ++k) s += txbuf[k][tid];
        out[xoff + tid] = s;
    }

    // ---- Cost: block-reduce then one scaled atomicAdd ----
#pragma unroll
    for (int m = 16; m >= 1; m >>= 1)
        costp += __shfl_xor_sync(0xffffffffu, costp, m);
    if (lane == 0) cbuf[warp] = costp;
    __syncthreads();
    if (tid == 0 && out_size > COST_IDX) {
        float tot = (cbuf[0] + cbuf[1] + cbuf[2] + cbuf[3]) * INV_CNT;
        atomicAdd(&out[COST_IDX], tot);
    }
}

extern "C" void kernel_launch(void* const* d_in, const int* in_sizes, int n_in,
                              void* d_out, int out_size) {
    const float* x     = (const float*)d_in[0];
    const float* P     = (const float*)d_in[1];
    const float* mask  = (const float*)d_in[2];
    const float* W     = (const float*)d_in[3];
    const float* bias  = (const float*)d_in[4];
    const float* gamma = (const float*)d_in[5];
    const float* beta  = (const float*)d_in[6];
    float* out = (float*)d_out;

    ot_prep_kernel<<<16, 256>>>(W, out, out_size);
    ot_main_kernel<<<NTOT, 128>>>(x, P, mask, bias, gamma, beta, out, out_size);
}

// round 3
// speedup vs baseline: 1.3954x; 1.3954x over previous
#include <cuda_runtime.h>
#include <cuda_bf16.h>
#include <cstdint>

// ---------------- problem constants ----------------
#define FEA      64
#define NTOT     14112
#define COST_IDX (NTOT * FEA)               /* 903168 */
#define INV_CNT  (1.0f / (14112.0f * 4096.0f))

// ---------------- smem layout (static, byte offsets) ----------------
// A tiles: 64 rows x 144B (64 bf16 + pad) per term
#define A_HI   0
#define A_LO   9216
#define B_HI   18432
#define B_LO   27648
#define S_XS   36864
#define S_MS   37120
#define S_BIAS 37376
#define S_GAM  37632
#define S_BET  37888
#define S_CRED 38144
#define SMEM_SZ 38208
// Pl (f32 [64][68]) overlays A_HI/A_LO after the MMA phase: 17408B < 18432B.

// ---------------- global scratch: W split into bf16 hi/lo ------------------
__device__ unsigned g_Whi32[2048];   // 4096 bf16, layout [h][g]
__device__ unsigned g_Wlo32[2048];

// ---------------- helpers ----------------
__device__ __forceinline__ uint32_t s2u(const void* p) {
    uint32_t a;
    asm("{ .reg .u64 t; cvta.to.shared.u64 t, %1; cvt.u32.u64 %0, t; }" : "=r"(a) : "l"(p));
    return a;
}

// split (x,y) into packed bf16x2 hi + bf16x2 lo residual
__device__ __forceinline__ void cvtpair(float x, float y, uint32_t& h, uint32_t& l) {
    asm("cvt.rn.bf16x2.f32 %0, %1, %2;" : "=r"(h) : "f"(y), "f"(x));
    float hx = __uint_as_float(h << 16);
    float hy = __uint_as_float(h & 0xffff0000u);
    float lx = x - hx, ly = y - hy;
    asm("cvt.rn.bf16x2.f32 %0, %1, %2;" : "=r"(l) : "f"(ly), "f"(lx));
}

#define LDSM_X4(r0, r1, r2, r3, addr) \
    asm volatile("ldmatrix.sync.aligned.m8n8.x4.shared.b16 {%0,%1,%2,%3}, [%4];" \
                 : "=r"(r0), "=r"(r1), "=r"(r2), "=r"(r3) : "r"(addr))

#define MMA_BF16(d, a, b) \
    asm volatile("mma.sync.aligned.m16n8k16.row.col.f32.bf16.bf16.f32 " \
                 "{%0,%1,%2,%3},{%4,%5,%6,%7},{%8,%9},{%0,%1,%2,%3};" \
                 : "+f"((d)[0]), "+f"((d)[1]), "+f"((d)[2]), "+f"((d)[3]) \
                 : "r"((a)[0]), "r"((a)[1]), "r"((a)[2]), "r"((a)[3]), \
                   "r"((b)[0]), "r"((b)[1]))

// ---------------- prep: split W to bf16 hi/lo, zero cost slot --------------
__global__ void ot_prep_kernel(const float* __restrict__ W,
                               float* __restrict__ out, int out_size) {
    int t = blockIdx.x * blockDim.x + threadIdx.x;
    if (t < 2048) {
        uint32_t h, l;
        cvtpair(W[2 * t], W[2 * t + 1], h, l);
        g_Whi32[t] = h;
        g_Wlo32[t] = l;
    }
    if (t == 0)
        for (int i = COST_IDX; i < out_size; ++i) out[i] = 0.0f;
}

// ---------------- main kernel: 1 CTA per problem, HMMA GEMM ----------------
__global__ void __launch_bounds__(128)
ot_mma_kernel(const float* __restrict__ x, const float* __restrict__ P,
              const float* __restrict__ mask, const float* __restrict__ bias,
              const float* __restrict__ gamma, const float* __restrict__ beta,
              float* __restrict__ out, int out_size) {

    __shared__ __align__(16) char smem[SMEM_SZ];
    const uint32_t sb = s2u(smem);

    const int n    = blockIdx.x;
    const int tid  = threadIdx.x;
    const int lane = tid & 31;
    const int wid  = tid >> 5;
    const int wy   = wid >> 1;         // M half
    const int wx   = wid & 1;          // N half

    float* xs_s   = (float*)(smem + S_XS);
    float* ms_s   = (float*)(smem + S_MS);
    float* bias_s = (float*)(smem + S_BIAS);
    float* gam_s  = (float*)(smem + S_GAM);
    float* bet_s  = (float*)(smem + S_BET);
    float* cred   = (float*)(smem + S_CRED);

    // n -> (b, v, p); x/out row base
    const int bb = n / (21 * 42);
    const int rm = n - bb * (21 * 42);
    const int vv = rm / 42;
    const int pp = rm - vv * 42;
    const size_t xob = ((size_t)(bb * 42 + pp) * 21 + vv) * FEA;

    // ---- load W tiles into smem (bf16 hi/lo, 144B padded rows) ----
#pragma unroll
    for (int k = 0; k < 4; ++k) {
        int idx = tid + (k << 7);              // [0,512) uint4
        int dst = (idx >> 3) * 144 + (idx & 7) * 16;
        *(uint4*)(smem + B_HI + dst) = ((const uint4*)g_Whi32)[idx];
        *(uint4*)(smem + B_LO + dst) = ((const uint4*)g_Wlo32)[idx];
    }

    // ---- load P, split to bf16 hi/lo, store padded ----
    const float4* P4 = (const float4*)(P + ((size_t)n << 12));
#pragma unroll
    for (int k = 0; k < 8; ++k) {
        int idx = tid + (k << 7);              // [0,1024) float4
        float4 u = P4[idx];
        uint32_t h0, l0, h1, l1;
        cvtpair(u.x, u.y, h0, l0);
        cvtpair(u.z, u.w, h1, l1);
        int dst = (idx >> 4) * 144 + (idx & 15) * 8;
        *(uint2*)(smem + A_HI + dst) = make_uint2(h0, h1);
        *(uint2*)(smem + A_LO + dst) = make_uint2(l0, l1);
    }
    if (tid < FEA) {
        xs_s[tid]   = x[xob + tid];
        ms_s[tid]   = mask[(size_t)n * FEA + tid];
        bias_s[tid] = bias[tid];
        gam_s[tid]  = gamma[tid];
        bet_s[tid]  = beta[tid];
    }
    __syncthreads();

    // ---- B fragments into registers (once): [nt][ks][2] per term ----
    uint32_t bh[4][4][2], bl[4][4][2];
    {
        const int brow = wx * 32 + (lane & 7) + ((lane & 16) >> 1); // +8 for tiles 2,3
        const int bcol = (lane & 8) * 2;                            // +16B for khalf1
#pragma unroll
        for (int np = 0; np < 2; ++np) {
            const int rbase = (brow + np * 16) * 144;
#pragma unroll
            for (int ks = 0; ks < 4; ++ks) {
                uint32_t ah = sb + B_HI + rbase + ks * 32 + bcol;
                uint32_t al = sb + B_LO + rbase + ks * 32 + bcol;
                LDSM_X4(bh[2*np][ks][0], bh[2*np][ks][1],
                        bh[2*np+1][ks][0], bh[2*np+1][ks][1], ah);
                LDSM_X4(bl[2*np][ks][0], bl[2*np][ks][1],
                        bl[2*np+1][ks][0], bl[2*np+1][ks][1], al);
            }
        }
    }

    // ---- GEMM: 96 HMMA (3 split terms) ----
    float acc[2][4][4];
#pragma unroll
    for (int m = 0; m < 2; ++m)
#pragma unroll
        for (int nt = 0; nt < 4; ++nt)
#pragma unroll
            for (int j = 0; j < 4; ++j) acc[m][nt][j] = 0.f;

    const int arow = wy * 32 + (lane & 15);
    const int acol = (lane & 16);               // +16B for khalf1
#pragma unroll
    for (int ks = 0; ks < 4; ++ks) {
#pragma unroll
        for (int m = 0; m < 2; ++m) {
            uint32_t aa = (arow + m * 16) * 144 + ks * 32 + acol;
            uint32_t ahr[4], alr[4];
            LDSM_X4(ahr[0], ahr[1], ahr[2], ahr[3], sb + A_HI + aa);
            LDSM_X4(alr[0], alr[1], alr[2], alr[3], sb + A_LO + aa);
#pragma unroll
            for (int nt = 0; nt < 4; ++nt) {
                MMA_BF16(acc[m][nt], ahr, bh[nt][ks]);
                MMA_BF16(acc[m][nt], alr, bh[nt][ks]);
                MMA_BF16(acc[m][nt], ahr, bl[nt][ks]);
            }
        }
    }
    __syncthreads();    // A tiles dead; Pl overlays them

    // ---- store acc -> Pl[64][68] f32 ----
    float* Pl = (float*)smem;
    {
        const int g4 = lane >> 2, t4 = lane & 3;
#pragma unroll
        for (int m = 0; m < 2; ++m) {
            const int r = wy * 32 + m * 16 + g4;
#pragma unroll
            for (int nt = 0; nt < 4; ++nt) {
                const int c = wx * 32 + nt * 8 + 2 * t4;
                *(float2*)&Pl[r * 68 + c]       = make_float2(acc[m][nt][0], acc[m][nt][1]);
                *(float2*)&Pl[(r + 8) * 68 + c] = make_float2(acc[m][nt][2], acc[m][nt][3]);
            }
        }
    }
    __syncthreads();

    // ---- epilogue: 2 threads per row (f = tid>>1, halves of 32) ----
    const int f   = tid >> 1;
    const int g0  = (tid & 1) << 5;
    float fv[32];
    float s1 = 0.f, s2 = 0.f;
#pragma unroll
    for (int q = 0; q < 8; ++q) {
        float4 pv = *(const float4*)&Pl[f * 68 + g0 + 4 * q];
        float4 bv = *(const float4*)(bias_s + g0 + 4 * q);
        float t0 = pv.x + bv.x, t1 = pv.y + bv.y;
        float t2 = pv.z + bv.z, t3 = pv.w + bv.w;
        fv[4*q+0] = t0; fv[4*q+1] = t1; fv[4*q+2] = t2; fv[4*q+3] = t3;
        s1 += t0 + t1 + t2 + t3;
        s2 += t0*t0 + t1*t1 + t2*t2 + t3*t3;
    }
    s1 += __shfl_xor_sync(0xffffffffu, s1, 1);
    s2 += __shfl_xor_sync(0xffffffffu, s2, 1);
    float mu   = s1 * (1.0f / 64.0f);
    float var  = s2 * (1.0f / 64.0f) - mu * mu;
    float rstd = rsqrtf(var + 1e-5f);

    float mx = -3.4e38f;
#pragma unroll
    for (int q = 0; q < 8; ++q) {
        float4 gv = *(const float4*)(gam_s + g0 + 4 * q);
        float4 ev = *(const float4*)(bet_s + g0 + 4 * q);
        float z0 = (fv[4*q+0] - mu) * rstd * gv.x + ev.x;
        float z1 = (fv[4*q+1] - mu) * rstd * gv.y + ev.y;
        float z2 = (fv[4*q+2] - mu) * rstd * gv.z + ev.z;
        float z3 = (fv[4*q+3] - mu) * rstd * gv.w + ev.w;
        fv[4*q+0] = z0; fv[4*q+1] = z1; fv[4*q+2] = z2; fv[4*q+3] = z3;
        mx = fmaxf(mx, fmaxf(fmaxf(z0, z1), fmaxf(z2, z3)));
    }
    mx = fmaxf(mx, __shfl_xor_sync(0xffffffffu, mx, 1));

    float se = 0.f;
#pragma unroll
    for (int g = 0; g < 32; ++g) {
        float e = __expf(fv[g] - mx);
        fv[g] = e;
        se += e;
    }
    se += __shfl_xor_sync(0xffffffffu, se, 1);
    float inv = __fdividef(1.0f, se);

    const float xf = xs_s[f];
    float costp = 0.f;
#pragma unroll
    for (int q = 0; q < 8; ++q) {
        float4 mv = *(const float4*)(ms_s + g0 + 4 * q);
        float p0 = fv[4*q+0] * inv, p1 = fv[4*q+1] * inv;
        float p2 = fv[4*q+2] * inv, p3 = fv[4*q+3] * inv;
        costp += p0 * mv.x + p1 * mv.y + p2 * mv.z + p3 * mv.w;
        // write xf * Ps back in place for the column sum
        *(float4*)&Pl[f * 68 + g0 + 4 * q] =
            make_float4(xf * p0, xf * p1, xf * p2, xf * p3);
    }
    __syncthreads();

    // ---- transport column sum + output ----
    if (tid < FEA) {
        float a0 = 0.f, a1 = 0.f, a2 = 0.f, a3 = 0.f;
#pragma unroll 4
        for (int ff = 0; ff < 64; ff += 4) {
            a0 += Pl[(ff + 0) * 68 + tid];
            a1 += Pl[(ff + 1) * 68 + tid];
            a2 += Pl[(ff + 2) * 68 + tid];
            a3 += Pl[(ff + 3) * 68 + tid];
        }
        out[xob + tid] = (a0 + a1) + (a2 + a3);
    }

    // ---- cost: block reduce + one RED ----
#pragma unroll
    for (int m = 16; m >= 1; m >>= 1)
        costp += __shfl_xor_sync(0xffffffffu, costp, m);
    if (lane == 0) cred[wid] = costp;
    __syncthreads();
    if (tid == 0 && out_size > COST_IDX)
        atomicAdd(&out[COST_IDX], (cred[0] + cred[1] + cred[2] + cred[3]) * INV_CNT);
}

extern "C" void kernel_launch(void* const* d_in, const int* in_sizes, int n_in,
                              void* d_out, int out_size) {
    const float* x     = (const float*)d_in[0];
    const float* P     = (const float*)d_in[1];
    const float* mask  = (const float*)d_in[2];
    const float* W     = (const float*)d_in[3];
    const float* bias  = (const float*)d_in[4];
    const float* gamma = (const float*)d_in[5];
    const float* beta  = (const float*)d_in[6];
    float* out = (float*)d_out;

    ot_prep_kernel<<<8, 256>>>(W, out, out_size);
    ot_mma_kernel<<<NTOT, 128>>>(x, P, mask, bias, gamma, beta, out, out_size);
}